// round 5
// baseline (speedup 1.0000x reference)
#include <cuda_runtime.h>

#define B_ 32
#define L_ 128
#define D_ 48
#define R_ 64
#define OUTSZ (B_*R_*D_)   // 98304

#define BG 4    // batch groups  (8 b per CTA)
#define RG 4    // r groups      (16 r per CTA)
#define LS 16   // l slices      (8 l per CTA)
#define BPC 8
#define RPC 16
#define LPC 8
#define NGRP (BG*RG)

__device__ float g_scratch[LS * OUTSZ];   // 6.3 MB partials
__device__ int   g_cnt[NGRP];

#define EX2(dst, a) asm("ex2.approx.ftz.f32 %0, %1;" : "=f"(dst) : "f"(a))

__global__ __launch_bounds__(192, 3) void alnn_main(
    const float* __restrict__ X, const float* __restrict__ T,
    const float* __restrict__ M, const float* __restrict__ DT,
    const float* __restrict__ P, const float* __restrict__ alpha,
    const float* __restrict__ w_t, const float* __restrict__ b_t,
    const float* __restrict__ w_v, const float* __restrict__ b_v,
    float* __restrict__ out)
{
    const int c  = blockIdx.x;          // 256 = BG*RG*LS
    const int ls = c & 15;
    const int rg = (c >> 4) & 3;
    const int bg = c >> 6;

    const int tid = threadIdx.x;        // 192 = 4 rs * 48 d
    const int d  = tid % D_;
    const int rs = tid / D_;            // 0..3
    const int b0 = bg * BPC;
    const int r0 = rg * RPC;
    const int l0 = ls * LPC;

    // smem input stage: [buf][field][b][d], fields: x,t,m,dt,p,xr
    __shared__ __align__(16) float sin_[2][6][BPC][D_];
    __shared__ int s_last;

    // per-thread r constants (r = r0 + rs*4 + k)
    float na[4], rr[4];
#pragma unroll
    for (int k = 0; k < 4; k++) {
        const int r = r0 + rs * 4 + k;
        na[k] = -fmaxf(alpha[r], 0.0f) * 1.4426950408889634f;
        rr[k] = (float)r * (48.0f / 63.0f);
    }

    float acc[4][BPC];
#pragma unroll
    for (int k = 0; k < 4; k++)
#pragma unroll
        for (int b = 0; b < BPC; b++) acc[k][b] = 0.0f;

    // ---- staging helpers (480 float4 chunks: 5 fields x 8 b x 12 dquads) ----
    // load phase -> registers, store phase -> smem (software pipeline)
    float4 stv[3];

    auto stage_load = [&](int l) {
#pragma unroll
        for (int q = 0; q < 3; q++) {
            const int u = tid + q * 192;
            if (u < 480) {
                const int f  = u / 96;
                const int rm = u % 96;
                const int b  = rm / 12;
                const int dq = rm % 12;
                const float* src = (f == 0) ? X : (f == 1) ? T : (f == 2) ? M
                                 : (f == 3) ? DT : P;
                stv[q] = *(const float4*)&src[((size_t)(b0 + b) * L_ + l) * D_ + dq * 4];
            }
        }
    };
    auto stage_store = [&](int buf) {
#pragma unroll
        for (int q = 0; q < 3; q++) {
            const int u = tid + q * 192;
            if (u < 480) {
                const int f  = u / 96;
                const int rm = u % 96;
                const int b  = rm / 12;
                const int dq = rm % 12;
                *(float4*)&sin_[buf][f][b][dq * 4] = stv[q];
                if (f == 0) {   // xr = relu(x) as field 5
                    float4 xr;
                    xr.x = fmaxf(stv[q].x, 0.0f);
                    xr.y = fmaxf(stv[q].y, 0.0f);
                    xr.z = fmaxf(stv[q].z, 0.0f);
                    xr.w = fmaxf(stv[q].w, 0.0f);
                    *(float4*)&sin_[buf][5][b][dq * 4] = xr;
                }
            }
        }
    };

    // prologue: stage l0 into buf 0
    stage_load(l0);
    stage_store(0);
    __syncthreads();

#pragma unroll 1
    for (int j = 0; j < LPC; j++) {
        const int l = l0 + j;
        const int buf = j & 1;

        // issue next stage's loads early (hide LDG latency under compute)
        if (j + 1 < LPC) stage_load(l + 1);

        // load this l's weights for the 4 owned r's
        float w[4][7];
#pragma unroll
        for (int k = 0; k < 4; k++) {
            const int wi = ((r0 + rs * 4 + k) * L_ + l) * D_ + d;
            const float* wt = w_t + (size_t)wi * 5;
            w[k][0] = wt[0]; w[k][1] = wt[1]; w[k][2] = wt[2];
            w[k][3] = wt[3]; w[k][4] = wt[4];
            w[k][5] = 5.0f * b_t[wi];
            w[k][6] = w_v[wi];
        }

#pragma unroll
        for (int b = 0; b < BPC; b++) {
            const float xv  = sin_[buf][0][b][d];
            const float tv  = sin_[buf][1][b][d];
            const float mv  = sin_[buf][2][b][d];
            const float dtv = sin_[buf][3][b][d];
            const float pv  = sin_[buf][4][b][d];
            const float xrv = sin_[buf][5][b][d];
#pragma unroll
            for (int k = 0; k < 4; k++) {
                const float arg = na[k] * fabsf(tv - rr[k]);
                float e; EX2(e, arg);
                const float inten = xrv * e;
                float s = fmaf(w[k][0], xv, w[k][5]);
                s = fmaf(w[k][1], inten, s);
                s = fmaf(w[k][2], mv,  s);
                s = fmaf(w[k][3], dtv, s);
                s = fmaf(w[k][4], pv,  s);
                s = fmaxf(s, 0.0f);
                acc[k][b] = fmaf(w[k][6], s, acc[k][b]);
            }
        }

        if (j + 1 < LPC) stage_store(buf ^ 1);
        __syncthreads();
    }

    // ---- write partials for this l-slice ----
#pragma unroll
    for (int k = 0; k < 4; k++) {
        const int r = r0 + rs * 4 + k;
#pragma unroll
        for (int b = 0; b < BPC; b++)
            g_scratch[ls * OUTSZ + (((b0 + b) * R_) + r) * D_ + d] = acc[k][b];
    }

    // ---- last CTA of (bg,rg) reduces the 16 l-slices ----
    __threadfence();
    __syncthreads();
    if (tid == 0) {
        const int old = atomicAdd(&g_cnt[bg * RG + rg], 1);
        s_last = (old == LS - 1);
    }
    __syncthreads();
    if (!s_last) return;
    if (tid == 0) g_cnt[bg * RG + rg] = 0;   // reset for next graph replay
    __threadfence();

    // 6144 outputs for this (bg,rg) = 1536 float4 quads; 8 quads per thread
#pragma unroll 1
    for (int u = tid; u < BPC * RPC * (D_ / 4); u += 192) {
        const int dq = u % 12;
        const int r  = (u / 12) % RPC + r0;
        const int b  = u / (12 * RPC) + b0;
        const int idx = ((b * R_ + r) * D_) / 4 + dq;   // float4 index
        float4 bv = *(const float4*)&b_v[r * D_ + dq * 4];
        float4 s;
        s.x = 128.0f * bv.x; s.y = 128.0f * bv.y;
        s.z = 128.0f * bv.z; s.w = 128.0f * bv.w;
#pragma unroll
        for (int sl = 0; sl < LS; sl++) {
            const float4 v = *(const float4*)&g_scratch[sl * OUTSZ + idx * 4];
            s.x += v.x; s.y += v.y; s.z += v.z; s.w += v.w;
        }
        s.x = fmaxf(s.x, 0.0f); s.y = fmaxf(s.y, 0.0f);
        s.z = fmaxf(s.z, 0.0f); s.w = fmaxf(s.w, 0.0f);
        *(float4*)&out[idx * 4] = s;
    }
}

extern "C" void kernel_launch(void* const* d_in, const int* in_sizes, int n_in,
                              void* d_out, int out_size)
{
    const float* X     = (const float*)d_in[0];
    const float* T     = (const float*)d_in[1];
    const float* M     = (const float*)d_in[2];
    const float* DT    = (const float*)d_in[3];
    const float* P     = (const float*)d_in[4];
    const float* alpha = (const float*)d_in[5];
    const float* w_t   = (const float*)d_in[6];
    const float* b_t   = (const float*)d_in[7];
    const float* w_v   = (const float*)d_in[8];
    const float* b_v   = (const float*)d_in[9];
    float* out = (float*)d_out;

    alnn_main<<<BG * RG * LS, 192>>>(X, T, M, DT, P, alpha, w_t, b_t, w_v, b_v, out);
}

// round 6
// speedup vs baseline: 1.1530x; 1.1530x over previous
#include <cuda_runtime.h>

#define B_ 32
#define L_ 128
#define D_ 48
#define R_ 64
#define OUTSZ (B_*R_*D_)   // 98304

#define BG 4     // batch groups (8 b per CTA)  -> weights read x4
#define RG 4     // r groups (16 r per CTA)     -> inputs read x4
#define LSN 16   // l slices (8 l per CTA)
#define BPC 8
#define RPC 16
#define LPC 8
#define NGRP (BG*RG)

__device__ float g_scratch[LSN * OUTSZ];   // 6.3 MB partials
__device__ int   g_cnt[NGRP];

#define EX2(dst, a) asm("ex2.approx.ftz.f32 %0, %1;" : "=f"(dst) : "f"(a))

__global__ __launch_bounds__(384, 2) void alnn_main(
    const float* __restrict__ X, const float* __restrict__ T,
    const float* __restrict__ M, const float* __restrict__ DT,
    const float* __restrict__ P, const float* __restrict__ alpha,
    const float* __restrict__ w_t, const float* __restrict__ b_t,
    const float* __restrict__ w_v, const float* __restrict__ b_v,
    float* __restrict__ out)
{
    const int c  = blockIdx.x;          // 256 = BG*RG*LSN
    const int ls = c & 15;
    const int rg = (c >> 4) & 3;
    const int bg = c >> 6;

    const int tid = threadIdx.x;        // 384 = 8 rs * 48 d
    const int d  = tid % D_;
    const int rs = tid / D_;            // 0..7, owns 2 r's
    const int b0 = bg * BPC;
    const int r0 = rg * RPC;
    const int l0 = ls * LPC;

    // double-buffered input stage: [buf][field][b][d], fields: x,t,m,dt,p
    __shared__ __align__(16) float sin_[2][5][BPC][D_];   // 15.4 KB
    __shared__ int s_last;

    float na[2], rr[2];
#pragma unroll
    for (int k = 0; k < 2; k++) {
        const int r = r0 + rs * 2 + k;
        na[k] = -fmaxf(alpha[r], 0.0f) * 1.4426950408889634f;
        rr[k] = (float)r * (48.0f / 63.0f);
    }

    float acc[2][BPC];
#pragma unroll
    for (int k = 0; k < 2; k++)
#pragma unroll
        for (int b = 0; b < BPC; b++) acc[k][b] = 0.0f;

    // --- cp.async staging of one l's inputs: 480 x 16B over 384 threads ---
    auto stage = [&](int l, int buf) {
#pragma unroll
        for (int q = 0; q < 2; q++) {
            const int u = tid + q * 384;
            if (u < 480) {
                const int f  = u / 96;
                const int rm = u % 96;
                const int b  = rm / 12;
                const int dq = rm % 12;
                const float* src = (f == 0) ? X : (f == 1) ? T : (f == 2) ? M
                                 : (f == 3) ? DT : P;
                const float* gp = &src[((size_t)(b0 + b) * L_ + l) * D_ + dq * 4];
                const unsigned sa =
                    (unsigned)__cvta_generic_to_shared(&sin_[buf][f][b][dq * 4]);
                asm volatile("cp.async.cg.shared.global [%0], [%1], 16;"
                             :: "r"(sa), "l"(gp) : "memory");
            }
        }
        asm volatile("cp.async.commit_group;" ::: "memory");
    };

    auto load_w = [&](int l, float w[2][7]) {
#pragma unroll
        for (int k = 0; k < 2; k++) {
            const int wi = ((r0 + rs * 2 + k) * L_ + l) * D_ + d;
            const float* wt = w_t + (size_t)wi * 5;
            w[k][0] = wt[0]; w[k][1] = wt[1]; w[k][2] = wt[2];
            w[k][3] = wt[3]; w[k][4] = wt[4];
            w[k][5] = 5.0f * b_t[wi];
            w[k][6] = w_v[wi];
        }
    };

    // prologue: stage inputs(l0) and weights(l0)
    stage(l0, 0);
    float wc[2][7];
    load_w(l0, wc);
    asm volatile("cp.async.wait_group 0;" ::: "memory");
    __syncthreads();

#pragma unroll 1
    for (int j = 0; j < LPC; j++) {
        const int buf = j & 1;

        // issue next iteration's inputs + weights up front (full-body latency cover)
        if (j + 1 < LPC) stage(l0 + j + 1, buf ^ 1);
        float wn[2][7];
        if (j + 1 < LPC) load_w(l0 + j + 1, wn);

#pragma unroll
        for (int b = 0; b < BPC; b++) {
            const float xv  = sin_[buf][0][b][d];
            const float tv  = sin_[buf][1][b][d];
            const float mv  = sin_[buf][2][b][d];
            const float dtv = sin_[buf][3][b][d];
            const float pv  = sin_[buf][4][b][d];
            const float xr  = fmaxf(xv, 0.0f);
#pragma unroll
            for (int k = 0; k < 2; k++) {
                const float arg = na[k] * fabsf(tv - rr[k]);
                float e; EX2(e, arg);
                const float inten = xr * e;          // relu(x)*k == relu(x*k)
                float s = fmaf(wc[k][0], xv, wc[k][5]);
                s = fmaf(wc[k][1], inten, s);
                s = fmaf(wc[k][2], mv,  s);
                s = fmaf(wc[k][3], dtv, s);
                s = fmaf(wc[k][4], pv,  s);
                s = fmaxf(s, 0.0f);
                acc[k][b] = fmaf(wc[k][6], s, acc[k][b]);
            }
        }

        if (j + 1 < LPC) {
            asm volatile("cp.async.wait_group 0;" ::: "memory");
            __syncthreads();
#pragma unroll
            for (int k = 0; k < 2; k++)
#pragma unroll
                for (int q = 0; q < 7; q++) wc[k][q] = wn[k][q];
        }
    }

    // ---- write partials for this l-slice ----
#pragma unroll
    for (int k = 0; k < 2; k++) {
        const int r = r0 + rs * 2 + k;
#pragma unroll
        for (int b = 0; b < BPC; b++)
            g_scratch[ls * OUTSZ + (((b0 + b) * R_) + r) * D_ + d] = acc[k][b];
    }

    // ---- last CTA of (bg,rg) reduces the 16 l-slices ----
    __threadfence();
    __syncthreads();
    if (tid == 0) {
        const int old = atomicAdd(&g_cnt[bg * RG + rg], 1);
        s_last = (old == LSN - 1);
    }
    __syncthreads();
    if (!s_last) return;
    if (tid == 0) g_cnt[bg * RG + rg] = 0;   // reset for next graph replay
    __threadfence();

    // 6144 outputs for this (bg,rg) = 1536 float4 quads; 4 per thread
#pragma unroll 1
    for (int u = tid; u < BPC * RPC * (D_ / 4); u += 384) {
        const int dq = u % 12;
        const int r  = (u / 12) % RPC + r0;
        const int b  = u / (12 * RPC) + b0;
        const int idx = ((b * R_ + r) * D_) / 4 + dq;
        const float4 bv = *(const float4*)&b_v[r * D_ + dq * 4];
        float4 s;
        s.x = 128.0f * bv.x; s.y = 128.0f * bv.y;
        s.z = 128.0f * bv.z; s.w = 128.0f * bv.w;
#pragma unroll
        for (int sl = 0; sl < LSN; sl++) {
            const float4 v = *(const float4*)&g_scratch[sl * OUTSZ + idx * 4];
            s.x += v.x; s.y += v.y; s.z += v.z; s.w += v.w;
        }
        s.x = fmaxf(s.x, 0.0f); s.y = fmaxf(s.y, 0.0f);
        s.z = fmaxf(s.z, 0.0f); s.w = fmaxf(s.w, 0.0f);
        *(float4*)&out[idx * 4] = s;
    }
}

extern "C" void kernel_launch(void* const* d_in, const int* in_sizes, int n_in,
                              void* d_out, int out_size)
{
    const float* X     = (const float*)d_in[0];
    const float* T     = (const float*)d_in[1];
    const float* M     = (const float*)d_in[2];
    const float* DT    = (const float*)d_in[3];
    const float* P     = (const float*)d_in[4];
    const float* alpha = (const float*)d_in[5];
    const float* w_t   = (const float*)d_in[6];
    const float* b_t   = (const float*)d_in[7];
    const float* w_v   = (const float*)d_in[8];
    const float* b_v   = (const float*)d_in[9];
    float* out = (float*)d_out;

    alnn_main<<<BG * RG * LSN, 384>>>(X, T, M, DT, P, alpha, w_t, b_t, w_v, b_v, out);
}

// round 7
// speedup vs baseline: 1.3776x; 1.1949x over previous
#include <cuda_runtime.h>

#define B_ 32
#define L_ 128
#define D_ 48
#define R_ 64
#define OUTSZ (B_*R_*D_)   // 98304
#define NGRP 32            // 4 bg x 8 rg

typedef unsigned long long ull;

// 8 partial slices (one per L-split) of (B,R,D)
__device__ float g_scratch[8 * OUTSZ];
__device__ int   g_cnt[NGRP];

#define PACK2(dst, lo, hi) \
    asm("mov.b64 %0, {%1, %2};" : "=l"(dst) : "r"(__float_as_uint(lo)), "r"(__float_as_uint(hi)))
#define UNPACK2(lo, hi, src) do { unsigned _a, _b; \
    asm("mov.b64 {%0, %1}, %2;" : "=r"(_a), "=r"(_b) : "l"(src)); \
    lo = __uint_as_float(_a); hi = __uint_as_float(_b); } while(0)
#define ADD2(d, a, b)  asm("add.rn.f32x2 %0, %1, %2;" : "=l"(d) : "l"(a), "l"(b))
#define MUL2(d, a, b)  asm("mul.rn.f32x2 %0, %1, %2;" : "=l"(d) : "l"(a), "l"(b))
#define FMA2ACC(acc, a, b) asm("fma.rn.f32x2 %0, %1, %2, %0;" : "+l"(acc) : "l"(a), "l"(b))
#define EX2(d, a)      asm("ex2.approx.ftz.f32 %0, %1;" : "=f"(d) : "f"(a))

__global__ __launch_bounds__(192, 2) void alnn_fused(
    const float* __restrict__ X, const float* __restrict__ T,
    const float* __restrict__ M, const float* __restrict__ DT,
    const float* __restrict__ P, const float* __restrict__ alpha,
    const float* __restrict__ w_t, const float* __restrict__ b_t,
    const float* __restrict__ w_v, const float* __restrict__ b_v,
    float* __restrict__ out)
{
    // Grid: 256 = 4 bg x 8 rg x 8 ls. Block: 192 = 4 lgroups x 48 d.
    const int c  = blockIdx.x;
    const int ls = c & 7;
    const int rg = (c >> 3) & 7;
    const int bg = c >> 6;

    const int tid = threadIdx.x;
    const int d = tid % D_;
    const int g = tid / D_;          // 0..3
    const int b0 = bg * 8;
    const int r0 = rg * 8;
    const int l0 = ls * 16 + g * 4;  // 4 l's per thread

    // -relu(alpha)*log2e per owned r (warp-uniform loads)
    float naa[8];
#pragma unroll
    for (int ri = 0; ri < 8; ri++)
        naa[ri] = -fmaxf(alpha[r0 + ri], 0.0f) * 1.4426950408889634f;

    ull acc2[4][8];
#pragma unroll
    for (int p = 0; p < 4; p++)
#pragma unroll
        for (int ri = 0; ri < 8; ri++) acc2[p][ri] = 0ull;

#pragma unroll 1
    for (int j = 0; j < 4; j++) {
        const int l = l0 + j;

        // Load inputs for 8 batches at (l,d), packed into 4 b-pairs
        ull xv2[4], xr2[4], tv2[4], mv2[4], dtv2[4], pv2[4];
#pragma unroll
        for (int p = 0; p < 4; p++) {
            const int i0 = ((b0 + 2*p) * L_ + l) * D_ + d;
            const int i1 = i0 + L_ * D_;
            const float x0 = X[i0], x1 = X[i1];
            PACK2(xv2[p], x0, x1);
            PACK2(xr2[p], fmaxf(x0, 0.0f), fmaxf(x1, 0.0f));
            PACK2(tv2[p],  T[i0],  T[i1]);
            PACK2(mv2[p],  M[i0],  M[i1]);
            PACK2(dtv2[p], DT[i0], DT[i1]);
            PACK2(pv2[p],  P[i0],  P[i1]);
        }

        const int wbase = (r0 * L_ + l) * D_ + d;

        // prefetch weights for ri=0
        float cw0, cw1, cw2, cw3, cw4, cw5, cw6;
        {
            const float* wt = w_t + (size_t)wbase * 5;
            cw0 = wt[0]; cw1 = wt[1]; cw2 = wt[2]; cw3 = wt[3]; cw4 = wt[4];
            cw5 = b_t[wbase];
            cw6 = w_v[wbase];
        }

#pragma unroll
        for (int ri = 0; ri < 8; ri++) {
            // issue next ri's weight loads before computing this ri
            float nw0, nw1, nw2, nw3, nw4, nw5, nw6;
            if (ri < 7) {
                const int wi = wbase + (ri + 1) * (L_ * D_);
                const float* wt = w_t + (size_t)wi * 5;
                nw0 = wt[0]; nw1 = wt[1]; nw2 = wt[2]; nw3 = wt[3]; nw4 = wt[4];
                nw5 = b_t[wi];
                nw6 = w_v[wi];
            }

            const float bt5 = 5.0f * cw5;
            const float wvh = 0.5f * cw6;           // fold relu's 1/2 into w_v (exact)
            const float nrr = -(float)(r0 + ri) * (48.0f / 63.0f);
            ull w0_2, w1_2, w2_2, w3_2, w4_2, bt2, wv2, rr2, aa2;
            PACK2(w0_2, cw0, cw0);  PACK2(w1_2, cw1, cw1);
            PACK2(w2_2, cw2, cw2);  PACK2(w3_2, cw3, cw3);
            PACK2(w4_2, cw4, cw4);  PACK2(bt2, bt5, bt5);
            PACK2(wv2, wvh, wvh);
            PACK2(rr2, nrr, nrr);
            PACK2(aa2, naa[ri], naa[ri]);

#pragma unroll
            for (int p = 0; p < 4; p++) {
                ull d2, m2, k2, i2, s2, hs2;
                ADD2(d2, tv2[p], rr2);                 // t - ref
                MUL2(m2, d2, aa2);                     // -a*(t-ref)
                ull arg2 = m2 | 0x8000000080000000ull; // -|a*(t-ref)|
                float e0, e1, k0, k1;
                UNPACK2(e0, e1, arg2);
                EX2(k0, e0); EX2(k1, e1);
                PACK2(k2, k0, k1);
                MUL2(i2, xr2[p], k2);                  // relu(x)*kernel
                s2 = bt2;
                FMA2ACC(s2, w0_2, xv2[p]);
                FMA2ACC(s2, w1_2, i2);
                FMA2ACC(s2, w2_2, mv2[p]);
                FMA2ACC(s2, w3_2, dtv2[p]);
                FMA2ACC(s2, w4_2, pv2[p]);
                const ull ab2 = s2 & 0x7fffffff7fffffffull;
                ADD2(hs2, s2, ab2);                    // 2*relu(s)
                FMA2ACC(acc2[p][ri], wv2, hs2);        // (w_v/2)*2*relu(s)
            }

            cw0 = nw0; cw1 = nw1; cw2 = nw2; cw3 = nw3; cw4 = nw4;
            cw5 = nw5; cw6 = nw6;
        }
    }

    // Intra-CTA reduction over the 4 l-groups, in 2 halves of 4 batches.
    __shared__ float sm[4 * 4 * 8 * D_];   // [g][bl][ri][d] = 24KB
    __shared__ int s_last;
#pragma unroll 1
    for (int h = 0; h < 2; h++) {
#pragma unroll
        for (int bl = 0; bl < 4; bl++) {
            const int p = h * 2 + (bl >> 1);
            const int hi = bl & 1;
#pragma unroll
            for (int ri = 0; ri < 8; ri++) {
                float lo, hv;
                UNPACK2(lo, hv, acc2[p][ri]);
                sm[((g * 4 + bl) * 8 + ri) * D_ + d] = hi ? hv : lo;
            }
        }
        __syncthreads();
#pragma unroll
        for (int k = 0; k < 8; k++) {
            const int idx = k * 192 + tid;             // 0..1535
            const float s = sm[idx] + sm[1536 + idx] + sm[2*1536 + idx] + sm[3*1536 + idx];
            const int dd = idx % D_;
            const int ri = (idx / D_) & 7;
            const int bl = idx / (8 * D_);
            const int b = b0 + h * 4 + bl;
            const int r = r0 + ri;
            g_scratch[ls * OUTSZ + (b * R_ + r) * D_ + dd] = s;
        }
        __syncthreads();
    }

    // ---- last CTA of (bg,rg) reduces the 8 l-slices and writes out ----
    __threadfence();
    if (tid == 0) {
        const int old = atomicAdd(&g_cnt[bg * 8 + rg], 1);
        s_last = (old == 7);
    }
    __syncthreads();
    if (!s_last) return;
    if (tid == 0) g_cnt[bg * 8 + rg] = 0;   // reset for next graph replay
    __threadfence();

    // 8b x 8r x 48d = 3072 outputs = 768 float4 quads; 4 per thread
#pragma unroll
    for (int s4 = 0; s4 < 4; s4++) {
        const int u  = tid + s4 * 192;      // 0..767
        const int dq = u % 12;
        const int r  = (u / 12) % 8 + r0;
        const int b  = u / 96 + b0;
        const int idx = (b * R_ + r) * D_ + dq * 4;
        const float4 bv = *(const float4*)&b_v[r * D_ + dq * 4];
        float4 s;
        s.x = 128.0f * bv.x; s.y = 128.0f * bv.y;
        s.z = 128.0f * bv.z; s.w = 128.0f * bv.w;
#pragma unroll
        for (int sl = 0; sl < 8; sl++) {
            const float4 v = *(const float4*)&g_scratch[sl * OUTSZ + idx];
            s.x += v.x; s.y += v.y; s.z += v.z; s.w += v.w;
        }
        s.x = fmaxf(s.x, 0.0f); s.y = fmaxf(s.y, 0.0f);
        s.z = fmaxf(s.z, 0.0f); s.w = fmaxf(s.w, 0.0f);
        *(float4*)&out[idx] = s;
    }
}

extern "C" void kernel_launch(void* const* d_in, const int* in_sizes, int n_in,
                              void* d_out, int out_size)
{
    const float* X     = (const float*)d_in[0];
    const float* T     = (const float*)d_in[1];
    const float* M     = (const float*)d_in[2];
    const float* DT    = (const float*)d_in[3];
    const float* P     = (const float*)d_in[4];
    const float* alpha = (const float*)d_in[5];
    const float* w_t   = (const float*)d_in[6];
    const float* b_t   = (const float*)d_in[7];
    const float* w_v   = (const float*)d_in[8];
    const float* b_v   = (const float*)d_in[9];
    float* out = (float*)d_out;

    alnn_fused<<<256, 192>>>(X, T, M, DT, P, alpha, w_t, b_t, w_v, b_v, out);
}